// round 1
// baseline (speedup 1.0000x reference)
#include <cuda_runtime.h>
#include <math.h>

// Problem constants
#define B_   32
#define H_   256
#define W_   1216
#define SH_  16
#define SW_  48
#define KH_  30     // int(2*256/17)
#define KW_  49     // int(2*1216/49)
#define HP_  227    // 256-30+1  (valid conv out H)
#define WP_  1168   // 1216-49+1 (valid conv out W)

#define N_SPARSE (B_*H_*W_)            // 9,961,472
#define N_DVT    (B_*H_*W_*2)          // 19,922,944
#define OUT_DVT_OFF   N_SPARSE
#define OUT_GRID_OFF  (N_SPARSE + N_DVT)  // 29,884,416

struct K30 { float v[KH_]; };
struct K49 { float v[KW_]; };

// scratch: vertical-conv result [b][c][i][w] as float4 over w (1216/4=304)
__device__ float4 g_vconv[B_ * 2 * SH_ * 304];

// ---------------------------------------------------------------------------
// Kernel 1: zero the sparse output region (float4 stores)
// ---------------------------------------------------------------------------
__global__ void k_zero(float4* __restrict__ out) {
    int i = blockIdx.x * blockDim.x + threadIdx.x;
    if (i < N_SPARSE / 4) out[i] = make_float4(0.f, 0.f, 0.f, 0.f);
}

// ---------------------------------------------------------------------------
// Kernel 2: dvf [b][c][h][w] -> out [b][h][w][c]   (float2 reads, float4 writes)
// ---------------------------------------------------------------------------
__global__ void k_transpose(const float2* __restrict__ in, float4* __restrict__ out) {
    const int HW2 = H_ * (W_ / 2);
    int idx = blockIdx.x * blockDim.x + threadIdx.x;
    if (idx >= B_ * HW2) return;
    int b  = idx / HW2;
    int hw = idx - b * HW2;
    float2 a = in[(b * 2 + 0) * HW2 + hw];   // channel 0, cols (2w2, 2w2+1)
    float2 c = in[(b * 2 + 1) * HW2 + hw];   // channel 1
    out[idx] = make_float4(a.x, c.x, a.y, c.y);
}

// ---------------------------------------------------------------------------
// Kernel 3: vertical Gaussian pass at the 16 needed row-windows
// grid = (i:16, bc:64), block = 304 threads (one float4 column-group each)
// ---------------------------------------------------------------------------
__global__ void k_vconv(const float4* __restrict__ dvf, K30 GH) {
    int i  = blockIdx.x;       // 0..15
    int bc = blockIdx.y;       // b*2+c, 0..63
    int t  = threadIdx.x;      // 0..303
    int h0 = (i * HP_) / SH_;  // window top row
    const float4* src = dvf + (bc * H_ + h0) * 304 + t;
    float4 acc = make_float4(0.f, 0.f, 0.f, 0.f);
#pragma unroll
    for (int r = 0; r < KH_; r++) {
        float4 v = src[r * 304];
        float  w = GH.v[r];
        acc.x += w * v.x; acc.y += w * v.y; acc.z += w * v.z; acc.w += w * v.w;
    }
    g_vconv[(bc * SH_ + i) * 304 + t] = acc;
}

// ---------------------------------------------------------------------------
// Kernel 4: horizontal pass -> svf -> grid_to_sample (write) -> bilinear
//           gather from gt -> scatter into sparse (row>=96 only).
// grid = 512 blocks (b*16+i), block = 128 threads
// ---------------------------------------------------------------------------
__global__ void k_grid_scatter(const float* __restrict__ gt,
                               float* __restrict__ out_sparse,
                               float2* __restrict__ out_grid,
                               K49 GW) {
    int b = blockIdx.x >> 4;
    int i = blockIdx.x & 15;
    int t = threadIdx.x;

    __shared__ float row[2][W_];
    __shared__ float gvals[2][SW_];

    // load both channel rows of vconv into smem
    for (int k = t; k < 2 * 304; k += 128) {
        int c = k / 304, w4 = k - c * 304;
        float4 v = g_vconv[((b * 2 + c) * SH_ + i) * 304 + w4];
        row[c][4 * w4 + 0] = v.x;
        row[c][4 * w4 + 1] = v.y;
        row[c][4 * w4 + 2] = v.z;
        row[c][4 * w4 + 3] = v.w;
    }
    __syncthreads();

    if (t < 96) {
        int c = t / SW_, j = t - c * SW_;
        int w0 = (j * WP_) / SW_;
        float acc = 0.f;
#pragma unroll
        for (int s = 0; s < KW_; s++) acc += GW.v[s] * row[c][w0 + s];
        float nrm = (c == 0) ? (2.0f * (float)j - 47.0f) * (1.0f / 48.0f)
                             : (2.0f * (float)i - 15.0f) * (1.0f / 16.0f);
        gvals[c][j] = acc + nrm;
    }
    __syncthreads();

    if (t < SW_) {
        int j = t;
        float gx = gvals[0][j];
        float gy = gvals[1][j];
        out_grid[(b * SH_ + i) * SW_ + j] = make_float2(gx, gy);

        // bilinear grid_sample (zeros padding, align_corners=False)
        float x = (gx + 1.0f) * ((float)W_ * 0.5f) - 0.5f;
        float y = (gy + 1.0f) * ((float)H_ * 0.5f) - 0.5f;
        float x0f = floorf(x), y0f = floorf(y);
        int x0 = (int)x0f, y0 = (int)y0f;
        int x1 = x0 + 1,   y1 = y0 + 1;
        float wx1 = x - x0f, wx0 = 1.0f - wx1;
        float wy1 = y - y0f, wy0 = 1.0f - wy1;

        const float* gtb = gt + (size_t)b * (H_ * W_);
        float v00 = 0.f, v01 = 0.f, v10 = 0.f, v11 = 0.f;
        bool yok0 = (y0 >= 0) && (y0 < H_);
        bool yok1 = (y1 >= 0) && (y1 < H_);
        bool xok0 = (x0 >= 0) && (x0 < W_);
        bool xok1 = (x1 >= 0) && (x1 < W_);
        if (yok0 && xok0) v00 = gtb[y0 * W_ + x0];
        if (yok0 && xok1) v01 = gtb[y0 * W_ + x1];
        if (yok1 && xok0) v10 = gtb[y1 * W_ + x0];
        if (yok1 && xok1) v11 = gtb[y1 * W_ + x1];
        float val = wy0 * wx0 * v00 + wy0 * wx1 * v01
                  + wy1 * wx0 * v10 + wy1 * wx1 * v11;

        // scatter index (truncation matches astype(int32) after the clip)
        float rf = (gy + 1.0f) * 0.5f * (float)H_;
        float cf = (gx + 1.0f) * 0.5f * (float)W_;
        int rI = (int)rf;  rI = rI < 0 ? 0 : (rI > H_ - 1 ? H_ - 1 : rI);
        int cI = (int)cf;  cI = cI < 0 ? 0 : (cI > W_ - 1 ? W_ - 1 : cI);
        if (rI >= 96) out_sparse[((size_t)b * H_ + rI) * W_ + cI] = val;
    }
}

// ---------------------------------------------------------------------------
extern "C" void kernel_launch(void* const* d_in, const int* in_sizes, int n_in,
                              void* d_out, int out_size) {
    const float* gt  = (const float*)d_in[0];
    const float* dvf = (const float*)d_in[1];
    float* out = (float*)d_out;

    // Gaussian weights in double, normalized per-axis (separable equivalent of
    // k = outer(gh,gw)/k.sum()).
    K30 GH; K49 GW;
    {
        double sh = (2.0 * (double)H_ / (double)(SH_ + 1)) / 3.0;  // 512/17/3
        double sw = (2.0 * (double)W_ / (double)(SW_ + 1)) / 3.0;  // 2432/49/3
        double g[KW_], s;
        s = 0.0;
        for (int r = 0; r < KH_; r++) {
            double u = ((double)r - (double)(KH_ - 1) / 2.0) / sh;
            g[r] = exp(-u * u / 2.0);
            s += g[r];
        }
        for (int r = 0; r < KH_; r++) GH.v[r] = (float)(g[r] / s);
        s = 0.0;
        for (int c = 0; c < KW_; c++) {
            double u = ((double)c - (double)(KW_ - 1) / 2.0) / sw;
            g[c] = exp(-u * u / 2.0);
            s += g[c];
        }
        for (int c = 0; c < KW_; c++) GW.v[c] = (float)(g[c] / s);
    }

    // 1) zero sparse region
    k_zero<<<(N_SPARSE / 4 + 255) / 256, 256>>>((float4*)out);
    // 2) dvf transpose -> out[OUT_DVT_OFF]  (also warms L2 with dvf for k_vconv)
    k_transpose<<<(B_ * H_ * (W_ / 2) + 255) / 256, 256>>>(
        (const float2*)dvf, (float4*)(out + OUT_DVT_OFF));
    // 3) vertical Gaussian pass
    k_vconv<<<dim3(16, 64), 304>>>((const float4*)dvf, GH);
    // 4) horizontal pass + grid write + bilinear sample + scatter
    k_grid_scatter<<<B_ * SH_, 128>>>(gt, out, (float2*)(out + OUT_GRID_OFF), GW);
}

// round 2
// speedup vs baseline: 1.0539x; 1.0539x over previous
#include <cuda_runtime.h>
#include <math.h>

// Problem constants
#define B_   32
#define H_   256
#define W_   1216
#define SH_  16
#define SW_  48
#define KH_  30     // int(2*256/17)
#define KW_  49     // int(2*1216/49)
#define HP_  227    // 256-30+1  (valid conv out H)
#define WP_  1168   // 1216-49+1 (valid conv out W)

#define N_SPARSE (B_*H_*W_)            // 9,961,472
#define N_DVT    (B_*H_*W_*2)          // 19,922,944
#define OUT_DVT_OFF   N_SPARSE
#define OUT_GRID_OFF  (N_SPARSE + N_DVT)  // 29,884,416

struct K30 { float v[KH_]; };
struct K49 { float v[KW_]; };

// ---------------------------------------------------------------------------
// Kernel 1: zero the sparse output region (float4 stores)
// ---------------------------------------------------------------------------
__global__ void k_zero(float4* __restrict__ out) {
    int i = blockIdx.x * blockDim.x + threadIdx.x;
    if (i < N_SPARSE / 4) out[i] = make_float4(0.f, 0.f, 0.f, 0.f);
}

// ---------------------------------------------------------------------------
// Kernel 2 (fused): vertical Gaussian pass -> smem row -> horizontal pass ->
//   grid_to_sample write -> bilinear gather from gt -> scatter into sparse.
// grid = (i:16, b:32), block = 608 threads (2 channels x 304 float4 columns)
// ---------------------------------------------------------------------------
__global__ void __launch_bounds__(608)
k_fused(const float4* __restrict__ dvf,
        const float* __restrict__ gt,
        float* __restrict__ out_sparse,
        float2* __restrict__ out_grid,
        K30 GH, K49 GW) {
    int i = blockIdx.x;   // sample row 0..15
    int b = blockIdx.y;   // batch
    int t = threadIdx.x;  // 0..607

    __shared__ float row[2][W_];

    // ---- vertical pass: 30-tap dot over rows for one (ch, w4) column ----
    int ch = t >= 304;
    int w4 = ch ? (t - 304) : t;
    int h0 = (i * HP_) >> 4;   // i*227/16
    const float4* src = dvf + (((size_t)(b * 2 + ch) * H_) + h0) * 304 + w4;
    float4 acc = make_float4(0.f, 0.f, 0.f, 0.f);
#pragma unroll
    for (int r = 0; r < KH_; r++) {
        float4 v = src[r * 304];
        float  w = GH.v[r];
        acc.x += w * v.x; acc.y += w * v.y; acc.z += w * v.z; acc.w += w * v.w;
    }
    *reinterpret_cast<float4*>(&row[ch][4 * w4]) = acc;
    __syncthreads();

    // ---- horizontal pass + epilogue: one thread per sample column j ----
    if (t < SW_) {
        int j = t;
        int w0 = (j * WP_) / SW_;
        float ax = 0.f, ay = 0.f;
#pragma unroll
        for (int s = 0; s < KW_; s++) {
            float w = GW.v[s];
            ax += w * row[0][w0 + s];
            ay += w * row[1][w0 + s];
        }
        float gx = ax + (2.0f * (float)j - 47.0f) * (1.0f / 48.0f);
        float gy = ay + (2.0f * (float)i - 15.0f) * (1.0f / 16.0f);
        out_grid[(b * SH_ + i) * SW_ + j] = make_float2(gx, gy);

        // bilinear grid_sample (zeros padding, align_corners=False)
        float x = (gx + 1.0f) * ((float)W_ * 0.5f) - 0.5f;
        float y = (gy + 1.0f) * ((float)H_ * 0.5f) - 0.5f;
        float x0f = floorf(x), y0f = floorf(y);
        int x0 = (int)x0f, y0 = (int)y0f;
        int x1 = x0 + 1,   y1 = y0 + 1;
        float wx1 = x - x0f, wx0 = 1.0f - wx1;
        float wy1 = y - y0f, wy0 = 1.0f - wy1;

        const float* gtb = gt + (size_t)b * (H_ * W_);
        float v00 = 0.f, v01 = 0.f, v10 = 0.f, v11 = 0.f;
        bool yok0 = (y0 >= 0) && (y0 < H_);
        bool yok1 = (y1 >= 0) && (y1 < H_);
        bool xok0 = (x0 >= 0) && (x0 < W_);
        bool xok1 = (x1 >= 0) && (x1 < W_);
        if (yok0 && xok0) v00 = gtb[y0 * W_ + x0];
        if (yok0 && xok1) v01 = gtb[y0 * W_ + x1];
        if (yok1 && xok0) v10 = gtb[y1 * W_ + x0];
        if (yok1 && xok1) v11 = gtb[y1 * W_ + x1];
        float val = wy0 * wx0 * v00 + wy0 * wx1 * v01
                  + wy1 * wx0 * v10 + wy1 * wx1 * v11;

        // scatter index (truncation matches astype(int32) after the clip)
        float rf = (gy + 1.0f) * 0.5f * (float)H_;
        float cf = (gx + 1.0f) * 0.5f * (float)W_;
        int rI = (int)rf;  rI = rI < 0 ? 0 : (rI > H_ - 1 ? H_ - 1 : rI);
        int cI = (int)cf;  cI = cI < 0 ? 0 : (cI > W_ - 1 ? W_ - 1 : cI);
        if (rI >= 96) out_sparse[((size_t)b * H_ + rI) * W_ + cI] = val;
    }
}

// ---------------------------------------------------------------------------
// Kernel 3: dvf [b][c][h][w] -> out [b][h][w][c]   (float2 reads, float4 writes)
// Runs LAST: after k_fused, dvf is L2-resident, so reads are L2 hits and
// this kernel is bound only by its 80 MB of stores.
// ---------------------------------------------------------------------------
__global__ void k_transpose(const float2* __restrict__ in, float4* __restrict__ out) {
    const int HW2 = H_ * (W_ / 2);
    int idx = blockIdx.x * blockDim.x + threadIdx.x;
    if (idx >= B_ * HW2) return;
    int b  = idx / HW2;
    int hw = idx - b * HW2;
    float2 a = in[(b * 2 + 0) * HW2 + hw];   // channel 0, cols (2w2, 2w2+1)
    float2 c = in[(b * 2 + 1) * HW2 + hw];   // channel 1
    out[idx] = make_float4(a.x, c.x, a.y, c.y);
}

// ---------------------------------------------------------------------------
extern "C" void kernel_launch(void* const* d_in, const int* in_sizes, int n_in,
                              void* d_out, int out_size) {
    const float* gt  = (const float*)d_in[0];
    const float* dvf = (const float*)d_in[1];
    float* out = (float*)d_out;

    // Gaussian weights in double, normalized per-axis (separable equivalent of
    // k = outer(gh,gw)/k.sum()).
    K30 GH; K49 GW;
    {
        double sh = (2.0 * (double)H_ / (double)(SH_ + 1)) / 3.0;  // 512/17/3
        double sw = (2.0 * (double)W_ / (double)(SW_ + 1)) / 3.0;  // 2432/49/3
        double g[KW_], s;
        s = 0.0;
        for (int r = 0; r < KH_; r++) {
            double u = ((double)r - (double)(KH_ - 1) / 2.0) / sh;
            g[r] = exp(-u * u / 2.0);
            s += g[r];
        }
        for (int r = 0; r < KH_; r++) GH.v[r] = (float)(g[r] / s);
        s = 0.0;
        for (int c = 0; c < KW_; c++) {
            double u = ((double)c - (double)(KW_ - 1) / 2.0) / sw;
            g[c] = exp(-u * u / 2.0);
            s += g[c];
        }
        for (int c = 0; c < KW_; c++) GW.v[c] = (float)(g[c] / s);
    }

    // 1) zero sparse region (must precede the scatter in k_fused)
    k_zero<<<(N_SPARSE / 4 + 255) / 256, 256>>>((float4*)out);
    // 2) fused vconv + hconv + grid write + bilinear sample + scatter
    k_fused<<<dim3(SH_, B_), 608>>>((const float4*)dvf, gt, out,
                                    (float2*)(out + OUT_GRID_OFF), GH, GW);
    // 3) dvf transpose -> out[OUT_DVT_OFF], reads dvf from hot L2
    k_transpose<<<(B_ * H_ * (W_ / 2) + 255) / 256, 256>>>(
        (const float2*)dvf, (float4*)(out + OUT_DVT_OFF));
}